// round 3
// baseline (speedup 1.0000x reference)
#include <cuda_runtime.h>
#include <cstdint>

#define B_ 4
#define N_ 2048
#define IND_ 256
#define H_ 4
#define D_ 64
#define HD_ 256
#define M_ (B_*N_)
#define NEG_SLOPE 0.2f
#define LOG2E 1.4426950408889634f

#define QT 256   // query tile per block
#define JT 64    // key chunk

// Scratch (static __device__ arrays; no allocation allowed)
__device__ float g_h[M_*HD_];        // 32 MB: h = x @ W, layout [B*N][H*D]
__device__ float g_src[M_*H_];
__device__ float g_dst[M_*H_];
__device__ unsigned g_maxdst[B_*H_]; // order-preserving-encoded float max

__global__ void k_init() {
    int t = threadIdx.x;
    if (t < B_*H_) g_maxdst[t] = 0u;
}

// ---------------------------------------------------------------------------
// Kernel 1: h = x @ W   (8192x256 @ 256x256), 64x64 tiles, 4x4 micro-kernel
// ---------------------------------------------------------------------------
__global__ __launch_bounds__(256) void k_gemm(const float* __restrict__ x,
                                              const float* __restrict__ W) {
    __shared__ float As[16][68];
    __shared__ float Bs[16][68];
    const int t  = threadIdx.x;
    const int m0 = blockIdx.x * 64;
    const int n0 = blockIdx.y * 64;
    const int tq = t >> 4, td = t & 15;
    const int am = t >> 2, ak4 = (t & 3) << 2;
    const int bk = t >> 4, bn4 = (t & 15) << 2;

    float acc[4][4];
    #pragma unroll
    for (int i = 0; i < 4; i++)
        #pragma unroll
        for (int j = 0; j < 4; j++) acc[i][j] = 0.f;

    for (int k0 = 0; k0 < IND_; k0 += 16) {
        float4 av = *(const float4*)(x + (m0 + am) * IND_ + k0 + ak4);
        float4 bv = *(const float4*)(W + (k0 + bk) * HD_ + n0 + bn4);
        __syncthreads();
        As[ak4 + 0][am] = av.x;
        As[ak4 + 1][am] = av.y;
        As[ak4 + 2][am] = av.z;
        As[ak4 + 3][am] = av.w;
        *(float4*)&Bs[bk][bn4] = bv;
        __syncthreads();
        #pragma unroll
        for (int k = 0; k < 16; k++) {
            float a0[4], b0[4];
            *(float4*)a0 = *(const float4*)&As[k][tq << 2];
            *(float4*)b0 = *(const float4*)&Bs[k][td << 2];
            #pragma unroll
            for (int i = 0; i < 4; i++)
                #pragma unroll
                for (int j = 0; j < 4; j++)
                    acc[i][j] = fmaf(a0[i], b0[j], acc[i][j]);
        }
    }
    #pragma unroll
    for (int i = 0; i < 4; i++)
        *(float4*)(g_h + (m0 + (tq << 2) + i) * HD_ + n0 + (td << 2)) = *(float4*)acc[i];
}

// ---------------------------------------------------------------------------
// Kernel 2: src/dst per (b,n,h) + per-(b,h) max of dst (encoded atomicMax)
// ---------------------------------------------------------------------------
__global__ __launch_bounds__(128) void k_srcdst(const float* __restrict__ a_src,
                                                const float* __restrict__ a_dst) {
    const int row  = blockIdx.x;
    const int h    = threadIdx.x >> 5;
    const int lane = threadIdx.x & 31;
    const float* hp = g_h + row * HD_ + h * D_;
    float v0 = hp[lane], v1 = hp[lane + 32];
    float s = v0 * a_src[h * D_ + lane] + v1 * a_src[h * D_ + lane + 32];
    float d = v0 * a_dst[h * D_ + lane] + v1 * a_dst[h * D_ + lane + 32];
    #pragma unroll
    for (int o = 16; o; o >>= 1) {
        s += __shfl_xor_sync(0xffffffffu, s, o);
        d += __shfl_xor_sync(0xffffffffu, d, o);
    }
    if (lane == 0) {
        g_src[row * H_ + h] = s;
        g_dst[row * H_ + h] = d;
        unsigned bits = __float_as_uint(d);
        unsigned enc  = (d >= 0.f) ? (bits | 0x80000000u) : ~bits;
        int b = row >> 11;
        atomicMax(&g_maxdst[b * H_ + h], enc);
    }
}

// ---------------------------------------------------------------------------
// Kernel 3: fused masked-softmax attention + AV, FFMA2 micro-kernel.
// 512 threads, q-tile 256, 4q x 8d per thread (32-reg f32x2 accumulator) to
// get occupancy to 16 warps/SM (4/SMSP). Pt swizzle keyed on (q>>2)&3.
// ---------------------------------------------------------------------------
__device__ __forceinline__ float ex2f(float x) {
    float r; asm("ex2.approx.f32 %0, %1;" : "=f"(r) : "f"(x)); return r;
}
__device__ __forceinline__ unsigned long long dupf(float v) {
    unsigned long long r;
    unsigned u = __float_as_uint(v);
    asm("mov.b64 %0, {%1, %1};" : "=l"(r) : "r"(u));
    return r;
}
#define FFMA2(d, a, b) asm("fma.rn.f32x2 %0, %1, %2, %0;" : "+l"(d) : "l"(a), "l"(b))

// smem float offsets
#define SM_KS   0
#define SM_PT   (JT * 64)                  // 4096
#define SM_DST  (SM_PT + QT * 64)          // + 16384
#define SM_SRC  (SM_DST + JT)
#define SM_CL   (SM_SRC + QT)
#define SM_LS   (SM_CL + QT)
#define SM_TOT  (SM_LS + QT)               // floats

__global__ __launch_bounds__(512, 1) void k_attn(const int* __restrict__ A_mask,
                                                 float* __restrict__ out) {
    extern __shared__ float sm[];
    float* Ks    = sm + SM_KS;
    float* Pt    = sm + SM_PT;
    float* sDst  = sm + SM_DST;
    float* sSrc  = sm + SM_SRC;
    float* sCl   = sm + SM_CL;
    float* sLsum = sm + SM_LS;

    const int t    = threadIdx.x;
    const int qt0  = blockIdx.x * QT;
    const int bh   = blockIdx.y;
    const int b    = bh >> 2, hh = bh & 3;
    const int rowbase = b * N_;
    const int tq = t >> 3, td = t & 7;   // GEMM: q = tq*4+i (i<4), d = td*8..td*8+7

    unsigned enc = g_maxdst[bh];
    float mdst = (enc & 0x80000000u) ? __uint_as_float(enc & 0x7fffffffu)
                                     : __uint_as_float(~enc);
    if (t < QT) {
        float s = g_src[(rowbase + qt0 + t) * H_ + hh];
        sSrc[t] = s;
        float l = s + mdst;                       // upper bound on src_i + dst_j
        float C = fmaxf(l, NEG_SLOPE * l);        // leaky_relu monotone -> bound
        sCl[t] = C * LOG2E;
    }

    float lsum[8];
    #pragma unroll
    for (int p = 0; p < 8; p++) lsum[p] = 0.f;
    unsigned long long acc[4][4];
    #pragma unroll
    for (int i = 0; i < 4; i++)
        #pragma unroll
        for (int c = 0; c < 4; c++) acc[i][c] = 0ull;

    for (int j0 = 0; j0 < N_; j0 += JT) {
        __syncthreads();
        // ---- Phase 1: stage Ks (granule-permuted) + sDst ----
        {
            #pragma unroll
            for (int p = 0; p < 2; p++) {
                int idx = p * 512 + t;
                int jr = idx >> 4;       // 0..63
                int g  = idx & 15;       // source granule (4 floats)
                int gp = (g >> 1) + ((g & 1) << 3);   // even g -> g/2, odd -> 8+g/2
                float4 v = *(const float4*)(g_h + (rowbase + j0 + jr) * HD_ + hh * D_ + (g << 2));
                *(float4*)&Ks[jr * 64 + (gp << 2)] = v;
            }
            if (t < JT) sDst[t] = g_dst[(rowbase + j0 + t) * H_ + hh];
        }
        __syncthreads();

        // ---- Phase 2: P tile [q][j], swizzle keyed on (q>>2)&3 ----
        {
            const int j4 = (t & 15) << 2;
            const int qb = t >> 4;                     // 0..31
            const int gp = (t & 15) ^ ((qb >> 2) & 3); // (q>>2)&3 == (qb>>2)&3, const over p
            float4 dv = *(const float4*)&sDst[j4];
            #pragma unroll
            for (int p = 0; p < 8; p++) {
                int q = qb + (p << 5);
                int4 m = *(const int4*)(A_mask + (qt0 + q) * N_ + j0 + j4);
                float s  = sSrc[q];
                float Cl = sCl[q];
                float l0 = s + dv.x, l1 = s + dv.y, l2 = s + dv.z, l3 = s + dv.w;
                l0 = fmaxf(l0, NEG_SLOPE * l0);
                l1 = fmaxf(l1, NEG_SLOPE * l1);
                l2 = fmaxf(l2, NEG_SLOPE * l2);
                l3 = fmaxf(l3, NEG_SLOPE * l3);
                float e0 = ex2f(fmaf(l0, LOG2E, -Cl));
                float e1 = ex2f(fmaf(l1, LOG2E, -Cl));
                float e2 = ex2f(fmaf(l2, LOG2E, -Cl));
                float e3 = ex2f(fmaf(l3, LOG2E, -Cl));
                e0 = m.x ? e0 : 0.f;
                e1 = m.y ? e1 : 0.f;
                e2 = m.z ? e2 : 0.f;
                e3 = m.w ? e3 : 0.f;
                lsum[p] += (e0 + e1) + (e2 + e3);
                *(float4*)&Pt[q * 64 + (gp << 2)] = make_float4(e0, e1, e2, e3);
            }
        }
        __syncthreads();

        // ---- Phase 3: acc += P^T-tile GEMM, FFMA2 pairs along d ----
        {
            #pragma unroll
            for (int jb = 0; jb < 16; jb++) {
                float4 p4[4];
                int gq = jb ^ (tq & 3);   // read back through the (q>>2)&3 swizzle
                #pragma unroll
                for (int i = 0; i < 4; i++)
                    p4[i] = *(const float4*)&Pt[(tq * 4 + i) * 64 + (gq << 2)];
                #pragma unroll
                for (int jj = 0; jj < 4; jj++) {
                    int j = (jb << 2) + jj;
                    ulonglong2 kl = *(const ulonglong2*)&Ks[j * 64 + (td << 2)];        // d = 8td..8td+3
                    ulonglong2 kh = *(const ulonglong2*)&Ks[j * 64 + 32 + (td << 2)];   // d = 8td+4..8td+7
                    #pragma unroll
                    for (int i = 0; i < 4; i++) {
                        float pv = (jj == 0) ? p4[i].x : (jj == 1) ? p4[i].y
                                 : (jj == 2) ? p4[i].z : p4[i].w;
                        unsigned long long pd = dupf(pv);
                        FFMA2(acc[i][0], pd, kl.x);
                        FFMA2(acc[i][1], pd, kl.y);
                        FFMA2(acc[i][2], pd, kh.x);
                        FFMA2(acc[i][3], pd, kh.y);
                    }
                }
            }
        }
    }

    // ---- lsum reduction: 16 consecutive threads share each q ----
    #pragma unroll
    for (int p = 0; p < 8; p++) {
        float v = lsum[p];
        v += __shfl_xor_sync(0xffffffffu, v, 1);
        v += __shfl_xor_sync(0xffffffffu, v, 2);
        v += __shfl_xor_sync(0xffffffffu, v, 4);
        v += __shfl_xor_sync(0xffffffffu, v, 8);
        if ((t & 15) == 0) sLsum[(t >> 4) + (p << 5)] = v;
    }
    __syncthreads();

    // ---- Epilogue: normalize + ELU + store ----
    #pragma unroll
    for (int i = 0; i < 4; i++) {
        int q = tq * 4 + i;
        float inv = 1.f / sLsum[q];
        float v[8];
        #pragma unroll
        for (int c = 0; c < 4; c++) {
            unsigned lo, hi;
            asm("mov.b64 {%0, %1}, %2;" : "=r"(lo), "=r"(hi) : "l"(acc[i][c]));
            v[2*c]   = __uint_as_float(lo) * inv;
            v[2*c+1] = __uint_as_float(hi) * inv;
        }
        #pragma unroll
        for (int c = 0; c < 8; c++)
            v[c] = (v[c] > 0.f) ? v[c] : expm1f(v[c]);
        float* op = out + (rowbase + qt0 + q) * HD_ + hh * D_ + td * 8;
        *(float4*)op       = make_float4(v[0], v[1], v[2], v[3]);
        *(float4*)(op + 4) = make_float4(v[4], v[5], v[6], v[7]);
    }
}

// ---------------------------------------------------------------------------
extern "C" void kernel_launch(void* const* d_in, const int* in_sizes, int n_in,
                              void* d_out, int out_size) {
    const float* x      = (const float*)d_in[0];
    const int*   A_mask = (const int*)d_in[1];
    const float* W      = (const float*)d_in[2];
    const float* a_src  = (const float*)d_in[3];
    const float* a_dst  = (const float*)d_in[4];
    float* out = (float*)d_out;

    cudaFuncSetAttribute(k_attn, cudaFuncAttributeMaxDynamicSharedMemorySize,
                         SM_TOT * (int)sizeof(float));

    k_init<<<1, 32>>>();
    k_gemm<<<dim3(M_ / 64, HD_ / 64), 256>>>(x, W);
    k_srcdst<<<M_, 128>>>(a_src, a_dst);
    k_attn<<<dim3(N_ / QT, B_ * H_), 512, SM_TOT * (int)sizeof(float)>>>(A_mask, out);
}

// round 4
// speedup vs baseline: 1.0775x; 1.0775x over previous
#include <cuda_runtime.h>
#include <cstdint>

#define B_ 4
#define N_ 2048
#define IND_ 256
#define H_ 4
#define D_ 64
#define HD_ 256
#define M_ (B_*N_)
#define NEG_SLOPE 0.2f
#define LOG2E 1.4426950408889634f

#define QT 256   // query tile per block
#define JT 64    // key chunk

// Scratch (static __device__ arrays; no allocation allowed)
__device__ float g_h[M_*HD_];          // 32 MB: h = x @ W, layout [B*N][H*D]
__device__ float g_srcT[B_*H_*N_];     // transposed: [bh][n]
__device__ float g_dstT[B_*H_*N_];
__device__ unsigned g_maxdst[B_*H_];   // order-preserving-encoded float max

__global__ void k_init() {
    int t = threadIdx.x;
    if (t < B_*H_) g_maxdst[t] = 0u;
}

__device__ __forceinline__ float ex2f(float x) {
    float r; asm("ex2.approx.f32 %0, %1;" : "=f"(r) : "f"(x)); return r;
}
__device__ __forceinline__ unsigned long long dupf(float v) {
    unsigned long long r;
    unsigned u = __float_as_uint(v);
    asm("mov.b64 %0, {%1, %1};" : "=l"(r) : "r"(u));
    return r;
}
#define FFMA2(d, a, b) asm("fma.rn.f32x2 %0, %1, %2, %0;" : "+l"(d) : "l"(a), "l"(b))

// ---------------------------------------------------------------------------
// Kernel 1: h = x @ W  (8192x256 @ 256x256), 64x64 tiles, FFMA2 micro-kernel
// (pairs along n: b-operand is a 16B smem read = 2 f32x2 pairs, a-scalar dup)
// ---------------------------------------------------------------------------
__global__ __launch_bounds__(256) void k_gemm(const float* __restrict__ x,
                                              const float* __restrict__ W) {
    __shared__ float As[16][68];
    __shared__ float Bs[16][68];
    const int t  = threadIdx.x;
    const int m0 = blockIdx.x * 64;
    const int n0 = blockIdx.y * 64;
    const int tq = t >> 4, td = t & 15;
    const int am = t >> 2, ak4 = (t & 3) << 2;
    const int bk = t >> 4, bn4 = (t & 15) << 2;

    unsigned long long acc[4][2];
    #pragma unroll
    for (int i = 0; i < 4; i++) { acc[i][0] = 0ull; acc[i][1] = 0ull; }

    for (int k0 = 0; k0 < IND_; k0 += 16) {
        float4 av = *(const float4*)(x + (m0 + am) * IND_ + k0 + ak4);
        float4 bv = *(const float4*)(W + (k0 + bk) * HD_ + n0 + bn4);
        __syncthreads();
        As[ak4 + 0][am] = av.x;
        As[ak4 + 1][am] = av.y;
        As[ak4 + 2][am] = av.z;
        As[ak4 + 3][am] = av.w;
        *(float4*)&Bs[bk][bn4] = bv;
        __syncthreads();
        #pragma unroll
        for (int k = 0; k < 16; k++) {
            float a0[4];
            *(float4*)a0 = *(const float4*)&As[k][tq << 2];
            ulonglong2 bl = *(const ulonglong2*)&Bs[k][td << 2];
            #pragma unroll
            for (int i = 0; i < 4; i++) {
                unsigned long long ad = dupf(a0[i]);
                FFMA2(acc[i][0], ad, bl.x);
                FFMA2(acc[i][1], ad, bl.y);
            }
        }
    }
    #pragma unroll
    for (int i = 0; i < 4; i++) {
        ulonglong2 o; o.x = acc[i][0]; o.y = acc[i][1];
        *(ulonglong2*)(g_h + (m0 + (tq << 2) + i) * HD_ + n0 + (td << 2)) = o;
    }
}

// ---------------------------------------------------------------------------
// Kernel 2: src/dst per (b,n,h), stored TRANSPOSED [bh][n]; per-(b,h) max dst
// ---------------------------------------------------------------------------
__global__ __launch_bounds__(128) void k_srcdst(const float* __restrict__ a_src,
                                                const float* __restrict__ a_dst) {
    const int row  = blockIdx.x;
    const int h    = threadIdx.x >> 5;
    const int lane = threadIdx.x & 31;
    const float* hp = g_h + row * HD_ + h * D_;
    float v0 = hp[lane], v1 = hp[lane + 32];
    float s = v0 * a_src[h * D_ + lane] + v1 * a_src[h * D_ + lane + 32];
    float d = v0 * a_dst[h * D_ + lane] + v1 * a_dst[h * D_ + lane + 32];
    #pragma unroll
    for (int o = 16; o; o >>= 1) {
        s += __shfl_xor_sync(0xffffffffu, s, o);
        d += __shfl_xor_sync(0xffffffffu, d, o);
    }
    if (lane == 0) {
        int b = row >> 11;
        int n = row & (N_ - 1);
        int bh = b * H_ + h;
        g_srcT[bh * N_ + n] = s;
        g_dstT[bh * N_ + n] = d;
        unsigned bits = __float_as_uint(d);
        unsigned enc  = (d >= 0.f) ? (bits | 0x80000000u) : ~bits;
        atomicMax(&g_maxdst[bh], enc);
    }
}

// ---------------------------------------------------------------------------
// Kernel 3: fused masked-softmax attention + AV, FFMA2, software-pipelined:
// double-buffered Ks/Pt, ONE barrier per chunk. Stage(c+1) and GEMM(c) live
// in one instruction stream so MUFU/LDG overlap FFMA2/LDS.
// ---------------------------------------------------------------------------

// smem float offsets (double-buffered Ks and Pt)
#define KS_SZ   (JT * 64)            // 4096
#define PT_SZ   (QT * 64)            // 16384
#define SM_KS   0
#define SM_PT   (2 * KS_SZ)
#define SM_SRC  (SM_PT + 2 * PT_SZ)
#define SM_CL   (SM_SRC + QT)
#define SM_LS   (SM_CL + QT)
#define SM_TOT  (SM_LS + QT)         // 41728 floats = 166912 B

__global__ __launch_bounds__(512, 1) void k_attn(const int* __restrict__ A_mask,
                                                 float* __restrict__ out) {
    extern __shared__ float sm[];
    float* KsB   = sm + SM_KS;
    float* PtB   = sm + SM_PT;
    float* sSrc  = sm + SM_SRC;
    float* sCl   = sm + SM_CL;
    float* sLsum = sm + SM_LS;

    const int t    = threadIdx.x;
    const int qt0  = blockIdx.x * QT;
    const int bh   = blockIdx.y;
    const int b    = bh >> 2, hh = bh & 3;
    const int rowbase = b * N_;
    const int tq = t >> 3, td = t & 7;   // GEMM: q = tq*4+i, d = td*8..td*8+7

    // staging index precomputes
    const int s_jr = t >> 4;                  // phase1 row (first half)
    const int s_g  = t & 15;                  // source granule
    const int s_gp = (s_g >> 1) + ((s_g & 1) << 3);
    const int p2_j4 = (t & 15) << 2;          // phase2 j offset
    const int p2_qb = t >> 4;                 // phase2 q base (0..31)
    const int p2_gp = (t & 15) ^ ((p2_qb >> 2) & 3);

    unsigned enc = g_maxdst[bh];
    float mdst = (enc & 0x80000000u) ? __uint_as_float(enc & 0x7fffffffu)
                                     : __uint_as_float(~enc);
    if (t < QT) {
        float s = g_srcT[bh * N_ + qt0 + t];
        sSrc[t] = s;
        float l = s + mdst;                   // upper bound on src_i + dst_j
        float C = fmaxf(l, NEG_SLOPE * l);    // leaky_relu monotone -> bound
        sCl[t] = C * LOG2E;
    }

    float lsum[8];
    #pragma unroll
    for (int p = 0; p < 8; p++) lsum[p] = 0.f;
    unsigned long long acc[4][4];
    #pragma unroll
    for (int i = 0; i < 4; i++)
        #pragma unroll
        for (int c = 0; c < 4; c++) acc[i][c] = 0ull;

    // ---- staging macro: chunk starting at j0 -> buffers Kd/Pd ----
#define STAGE(j0, Kd, Pd)                                                     \
    {                                                                         \
        const float* hsrc = g_h + (rowbase + (j0)) * HD_ + hh * D_;           \
        *(float4*)&(Kd)[s_jr * 64 + (s_gp << 2)] =                            \
            *(const float4*)(hsrc + s_jr * HD_ + (s_g << 2));                 \
        *(float4*)&(Kd)[(s_jr + 32) * 64 + (s_gp << 2)] =                     \
            *(const float4*)(hsrc + (s_jr + 32) * HD_ + (s_g << 2));          \
        float4 dv = *(const float4*)&g_dstT[bh * N_ + (j0) + p2_j4];          \
        _Pragma("unroll")                                                     \
        for (int p = 0; p < 8; p++) {                                         \
            int q = p2_qb + (p << 5);                                         \
            int4 m = *(const int4*)(A_mask + (qt0 + q) * N_ + (j0) + p2_j4);  \
            float s  = sSrc[q];                                               \
            float Cl = sCl[q];                                                \
            float l0 = s + dv.x, l1 = s + dv.y, l2 = s + dv.z, l3 = s + dv.w; \
            l0 = fmaxf(l0, NEG_SLOPE * l0);                                   \
            l1 = fmaxf(l1, NEG_SLOPE * l1);                                   \
            l2 = fmaxf(l2, NEG_SLOPE * l2);                                   \
            l3 = fmaxf(l3, NEG_SLOPE * l3);                                   \
            float e0 = ex2f(fmaf(l0, LOG2E, -Cl));                            \
            float e1 = ex2f(fmaf(l1, LOG2E, -Cl));                            \
            float e2 = ex2f(fmaf(l2, LOG2E, -Cl));                            \
            float e3 = ex2f(fmaf(l3, LOG2E, -Cl));                            \
            e0 = m.x ? e0 : 0.f;                                              \
            e1 = m.y ? e1 : 0.f;                                              \
            e2 = m.z ? e2 : 0.f;                                              \
            e3 = m.w ? e3 : 0.f;                                              \
            lsum[p] += (e0 + e1) + (e2 + e3);                                 \
            *(float4*)&(Pd)[q * 64 + (p2_gp << 2)] =                          \
                make_float4(e0, e1, e2, e3);                                  \
        }                                                                     \
    }

    // prologue: sSrc/sCl must be visible, then stage chunk 0 into buffer 0
    __syncthreads();
    STAGE(0, KsB, PtB);

    for (int c = 0; c < N_ / JT; c++) {
        const int cur = c & 1;
        float* Kc = KsB + cur * KS_SZ;
        float* Pc = PtB + cur * PT_SZ;
        __syncthreads();
        if (c < N_ / JT - 1) {
            float* Kn = KsB + (cur ^ 1) * KS_SZ;
            float* Pn = PtB + (cur ^ 1) * PT_SZ;
            STAGE((c + 1) * JT, Kn, Pn);
        }
        // ---- GEMM on current buffers: acc += P^T @ K, FFMA2 pairs along d ----
        #pragma unroll
        for (int jb = 0; jb < 16; jb++) {
            float4 p4[4];
            int gq = jb ^ (tq & 3);
            #pragma unroll
            for (int i = 0; i < 4; i++)
                p4[i] = *(const float4*)&Pc[(tq * 4 + i) * 64 + (gq << 2)];
            #pragma unroll
            for (int jj = 0; jj < 4; jj++) {
                int j = (jb << 2) + jj;
                ulonglong2 kl = *(const ulonglong2*)&Kc[j * 64 + (td << 2)];
                ulonglong2 kh = *(const ulonglong2*)&Kc[j * 64 + 32 + (td << 2)];
                #pragma unroll
                for (int i = 0; i < 4; i++) {
                    float pv = (jj == 0) ? p4[i].x : (jj == 1) ? p4[i].y
                             : (jj == 2) ? p4[i].z : p4[i].w;
                    unsigned long long pd = dupf(pv);
                    FFMA2(acc[i][0], pd, kl.x);
                    FFMA2(acc[i][1], pd, kl.y);
                    FFMA2(acc[i][2], pd, kh.x);
                    FFMA2(acc[i][3], pd, kh.y);
                }
            }
        }
    }
#undef STAGE

    // ---- lsum reduction: 16 consecutive threads share each q ----
    #pragma unroll
    for (int p = 0; p < 8; p++) {
        float v = lsum[p];
        v += __shfl_xor_sync(0xffffffffu, v, 1);
        v += __shfl_xor_sync(0xffffffffu, v, 2);
        v += __shfl_xor_sync(0xffffffffu, v, 4);
        v += __shfl_xor_sync(0xffffffffu, v, 8);
        if ((t & 15) == 0) sLsum[(t >> 4) + (p << 5)] = v;
    }
    __syncthreads();

    // ---- Epilogue: normalize + ELU + store ----
    #pragma unroll
    for (int i = 0; i < 4; i++) {
        int q = tq * 4 + i;
        float inv = 1.f / sLsum[q];
        float v[8];
        #pragma unroll
        for (int c = 0; c < 4; c++) {
            unsigned lo, hi;
            asm("mov.b64 {%0, %1}, %2;" : "=r"(lo), "=r"(hi) : "l"(acc[i][c]));
            v[2*c]   = __uint_as_float(lo) * inv;
            v[2*c+1] = __uint_as_float(hi) * inv;
        }
        #pragma unroll
        for (int c = 0; c < 8; c++)
            v[c] = (v[c] > 0.f) ? v[c] : expm1f(v[c]);
        float* op = out + (rowbase + qt0 + q) * HD_ + hh * D_ + td * 8;
        *(float4*)op       = make_float4(v[0], v[1], v[2], v[3]);
        *(float4*)(op + 4) = make_float4(v[4], v[5], v[6], v[7]);
    }
}

// ---------------------------------------------------------------------------
extern "C" void kernel_launch(void* const* d_in, const int* in_sizes, int n_in,
                              void* d_out, int out_size) {
    const float* x      = (const float*)d_in[0];
    const int*   A_mask = (const int*)d_in[1];
    const float* W      = (const float*)d_in[2];
    const float* a_src  = (const float*)d_in[3];
    const float* a_dst  = (const float*)d_in[4];
    float* out = (float*)d_out;

    cudaFuncSetAttribute(k_attn, cudaFuncAttributeMaxDynamicSharedMemorySize,
                         SM_TOT * (int)sizeof(float));

    k_init<<<1, 32>>>();
    k_gemm<<<dim3(M_ / 64, HD_ / 64), 256>>>(x, W);
    k_srcdst<<<M_, 128>>>(a_src, a_dst);
    k_attn<<<dim3(N_ / QT, B_ * H_), 512, SM_TOT * (int)sizeof(float)>>>(A_mask, out);
}

// round 7
// speedup vs baseline: 1.9381x; 1.7988x over previous
#include <cuda_runtime.h>
#include <cstdint>

#define B_ 4
#define N_ 2048
#define IND_ 256
#define H_ 4
#define D_ 64
#define HD_ 256
#define M_ (B_*N_)
#define NEG_SLOPE 0.2f
#define LOG2E 1.4426950408889634f

#define QTILE 128
#define JT 64
#define NCH (N_/JT)
#define NW (N_/32)      // bitmask words per row = 64

// Scratch (static __device__ arrays; no allocation allowed)
__device__ float g_hT[B_*H_*D_*N_];    // [bh][d][n], 8 MB
__device__ float g_srcT[B_*H_*N_];     // [bh][n]
__device__ float g_dstT[B_*H_*N_];
__device__ unsigned g_bm[N_*NW];       // bit-packed mask [q][w]
__device__ unsigned g_maxdst[B_*H_];

__global__ void k_init() {
    int t = threadIdx.x;
    if (t < B_*H_) g_maxdst[t] = 0u;
}

// ---------------------------------------------------------------------------
// helpers
// ---------------------------------------------------------------------------
__device__ __forceinline__ float ex2f(float x) {
    float r; asm("ex2.approx.f32 %0, %1;" : "=f"(r) : "f"(x)); return r;
}
__device__ __forceinline__ unsigned long long dupf(float v) {
    unsigned long long r;
    unsigned u = __float_as_uint(v);
    asm("mov.b64 %0, {%1, %1};" : "=l"(r) : "r"(u));
    return r;
}
#define FFMA2(d, a, b) asm("fma.rn.f32x2 %0, %1, %2, %0;" : "+l"(d) : "l"(a), "l"(b))

__device__ __forceinline__ uint32_t smem_u32(const void* p) {
    uint32_t a;
    asm("{ .reg .u64 tmp; cvta.to.shared.u64 tmp, %1; cvt.u32.u64 %0, tmp; }"
        : "=r"(a) : "l"(p));
    return a;
}
#define LDSM4(r0, r1, r2, r3, addr) \
    asm volatile("ldmatrix.sync.aligned.m8n8.x4.shared.b16 {%0,%1,%2,%3}, [%4];" \
                 : "=r"(r0), "=r"(r1), "=r"(r2), "=r"(r3) : "r"(addr))
#define MMA_TF32(d0, d1, d2, d3, a0, a1, a2, a3, b0, b1) \
    asm volatile("mma.sync.aligned.m16n8k8.row.col.f32.tf32.tf32.f32 " \
                 "{%0,%1,%2,%3}, {%4,%5,%6,%7}, {%8,%9}, {%0,%1,%2,%3};" \
                 : "+f"(d0), "+f"(d1), "+f"(d2), "+f"(d3) \
                 : "r"(a0), "r"(a1), "r"(a2), "r"(a3), "r"(b0), "r"(b1))

// ---------------------------------------------------------------------------
// Kernel: bit-pack the adjacency mask (16 reuses across b,h in k_attn)
// ---------------------------------------------------------------------------
__global__ __launch_bounds__(256) void k_bitpack(const int* __restrict__ A_mask) {
    int tid = blockIdx.x * 256 + threadIdx.x;          // 0 .. N_*NW-1
    const int4* p = (const int4*)(A_mask + tid * 32);  // row q = tid>>6, word w = tid&63
    unsigned bits = 0;
    #pragma unroll
    for (int i = 0; i < 8; i++) {
        int4 m = p[i];
        bits |= (unsigned)(m.x != 0) << (4*i)
             |  (unsigned)(m.y != 0) << (4*i+1)
             |  (unsigned)(m.z != 0) << (4*i+2)
             |  (unsigned)(m.w != 0) << (4*i+3);
    }
    g_bm[tid] = bits;
}

// ---------------------------------------------------------------------------
// Kernel 1: h = x @ W, FFMA2 micro-kernel, epilogue writes TRANSPOSED g_hT
// ---------------------------------------------------------------------------
__global__ __launch_bounds__(256) void k_gemm(const float* __restrict__ x,
                                              const float* __restrict__ W) {
    __shared__ float As[16][68];
    __shared__ float Bs[16][68];
    const int t  = threadIdx.x;
    const int m0 = blockIdx.x * 64;
    const int n0 = blockIdx.y * 64;
    const int tq = t >> 4, td = t & 15;
    const int am = t >> 2, ak4 = (t & 3) << 2;
    const int bk = t >> 4, bn4 = (t & 15) << 2;

    unsigned long long acc[4][2];
    #pragma unroll
    for (int i = 0; i < 4; i++) { acc[i][0] = 0ull; acc[i][1] = 0ull; }

    for (int k0 = 0; k0 < IND_; k0 += 16) {
        float4 av = *(const float4*)(x + (m0 + am) * IND_ + k0 + ak4);
        float4 bv = *(const float4*)(W + (k0 + bk) * HD_ + n0 + bn4);
        __syncthreads();
        As[ak4 + 0][am] = av.x;
        As[ak4 + 1][am] = av.y;
        As[ak4 + 2][am] = av.z;
        As[ak4 + 3][am] = av.w;
        *(float4*)&Bs[bk][bn4] = bv;
        __syncthreads();
        #pragma unroll
        for (int k = 0; k < 16; k++) {
            float a0[4];
            *(float4*)a0 = *(const float4*)&As[k][tq << 2];
            ulonglong2 bl = *(const ulonglong2*)&Bs[k][td << 2];
            #pragma unroll
            for (int i = 0; i < 4; i++) {
                unsigned long long ad = dupf(a0[i]);
                FFMA2(acc[i][0], ad, bl.x);
                FFMA2(acc[i][1], ad, bl.y);
            }
        }
    }
    // transpose epilogue: g_hT[bh][d][n]  (n-tile 64 == one head exactly)
    float fm[4][4];
    #pragma unroll
    for (int i = 0; i < 4; i++) {
        unsigned lo, hi;
        asm("mov.b64 {%0, %1}, %2;" : "=r"(lo), "=r"(hi) : "l"(acc[i][0]));
        fm[i][0] = __uint_as_float(lo); fm[i][1] = __uint_as_float(hi);
        asm("mov.b64 {%0, %1}, %2;" : "=r"(lo), "=r"(hi) : "l"(acc[i][1]));
        fm[i][2] = __uint_as_float(lo); fm[i][3] = __uint_as_float(hi);
    }
    const int b  = m0 >> 11;
    const int nn = m0 & (N_ - 1);
    const int bh = b * H_ + (n0 >> 6);
    float* bp = g_hT + (bh * D_ + td * 4) * N_ + nn + tq * 4;
    #pragma unroll
    for (int dd = 0; dd < 4; dd++)
        *(float4*)(bp + dd * N_) = make_float4(fm[0][dd], fm[1][dd], fm[2][dd], fm[3][dd]);
}

// ---------------------------------------------------------------------------
// Kernel 2: src/dst per (bh,n) from g_hT (coalesced along n) + max dst
// ---------------------------------------------------------------------------
__global__ __launch_bounds__(256) void k_srcdst(const float* __restrict__ a_src,
                                                const float* __restrict__ a_dst) {
    __shared__ float sa[64], sd[64], wmax[8];
    const int t  = threadIdx.x;
    const int bh = blockIdx.y;
    const int hh = bh & 3;
    const int n  = blockIdx.x * 256 + t;
    if (t < 64) { sa[t] = a_src[hh * 64 + t]; sd[t] = a_dst[hh * 64 + t]; }
    __syncthreads();
    const float* hp = g_hT + (bh * D_) * N_ + n;
    float s = 0.f, d = 0.f;
    #pragma unroll 8
    for (int dd = 0; dd < 64; dd++) {
        float v = hp[dd * N_];
        s = fmaf(v, sa[dd], s);
        d = fmaf(v, sd[dd], d);
    }
    g_srcT[bh * N_ + n] = s;
    g_dstT[bh * N_ + n] = d;
    float m = d;
    #pragma unroll
    for (int o = 16; o; o >>= 1) m = fmaxf(m, __shfl_xor_sync(0xffffffffu, m, o));
    if ((t & 31) == 0) wmax[t >> 5] = m;
    __syncthreads();
    if (t == 0) {
        float mm = wmax[0];
        #pragma unroll
        for (int i = 1; i < 8; i++) mm = fmaxf(mm, wmax[i]);
        unsigned bits = __float_as_uint(mm);
        unsigned enc  = (mm >= 0.f) ? (bits | 0x80000000u) : ~bits;
        atomicMax(&g_maxdst[bh], enc);
    }
}

// ---------------------------------------------------------------------------
// Kernel 3: fused masked-softmax attention + AV on mma.sync tf32 (m16n8k8).
// 256 threads, q-tile 128, chunks of 64 j. Pt[q][j] / Kt[d][j] smem tiles,
// 68-float row stride (conflict-free ldmatrix + STS). Warp w: q rows w*16..+15.
// ---------------------------------------------------------------------------
// smem float offsets
#define PT_OFF  0                      // 128 x 68
#define KT_OFF  (128 * 68)             // 64 x 68
#define SRC_OFF (KT_OFF + 64 * 68)
#define CL_OFF  (SRC_OFF + 128)
#define RED_OFF (CL_OFF + 128)
#define LS_OFF  (RED_OFF + 256)
#define SM_TOT  (LS_OFF + 128)         // floats

__global__ __launch_bounds__(256, 2) void k_attn(float* __restrict__ out) {
    extern __shared__ float sm[];
    float* Pt   = sm + PT_OFF;
    float* Kt   = sm + KT_OFF;
    float* sSrc = sm + SRC_OFF;
    float* sCl  = sm + CL_OFF;
    float* sRed = sm + RED_OFF;
    float* sLs  = sm + LS_OFF;

    const int t    = threadIdx.x;
    const int w    = t >> 5, lane = t & 31;
    const int qt0  = blockIdx.x * QTILE;
    const int bh   = blockIdx.y;
    const int b    = bh >> 2, hh = bh & 3;
    const int rowbase = b * N_;

    unsigned enc = g_maxdst[bh];
    float mdst = (enc & 0x80000000u) ? __uint_as_float(enc & 0x7fffffffu)
                                     : __uint_as_float(~enc);
    if (t < QTILE) {
        float s = g_srcT[bh * N_ + qt0 + t];
        sSrc[t] = s;
        float l = s + mdst;
        float C = fmaxf(l, NEG_SLOPE * l);
        sCl[t] = C * LOG2E;
    }
    __syncthreads();

    // ---- P-gen mapping: q = t&127, half = t>>7 (j range half*32..+31) ----
    const int pq   = t & 127;
    const int half = t >> 7;
    const float sv = sSrc[pq];
    const float Cl = sCl[pq];
    float* prow = Pt + pq * 68 + half * 32;

    // ---- Kt staging mapping: d = t>>2, 16 j per thread ----
    const int kd   = t >> 2;
    const int kj16 = (t & 3) << 4;
    float* krow = Kt + kd * 68 + kj16;
    const float* ksrc0 = g_hT + (bh * D_ + kd) * N_ + kj16;

    // ---- ldmatrix lane addresses (byte) ----
    const uint32_t smb = smem_u32(sm);
    const int lm = lane >> 3, lr = lane & 7;
    const int q0 = w * 16;
    // A frag: matrix 0:(q0..7, j0-3) 1:(q8..15, j0-3) 2:(q0..7, j4-7) 3:(q8..15, j4-7)
    const uint32_t aaddr0 = smb + (uint32_t)(((q0 + lr + ((lm & 1) << 3)) * 68
                                              + ((lm >> 1) << 2)) << 2);
    // B frags: pair p: matrices (nt=p, j0-3)(nt=p, j4-7)(nt=p+4, j0-3)(nt=p+4, j4-7)
    uint32_t baddr0[4];
    #pragma unroll
    for (int p = 0; p < 4; p++) {
        int nt = p + ((lm >> 1) << 2);           // lm<2 -> p, else p+4
        baddr0[p] = smb + (uint32_t)((KT_OFF + (nt * 8 + lr) * 68
                                      + ((lm & 1) << 2)) << 2);
    }

    float acc[8][4];
    #pragma unroll
    for (int n = 0; n < 8; n++)
        #pragma unroll
        for (int i = 0; i < 4; i++) acc[n][i] = 0.f;
    float lsum = 0.f;

    for (int c = 0; c < NCH; c++) {
        const int j0 = c * JT;
        __syncthreads();   // previous GEMM reads done before overwrite
        // ---- stage Kt[d][j] (coalesced from g_hT) ----
        {
            const float* ks = ksrc0 + j0;
            #pragma unroll
            for (int i = 0; i < 4; i++)
                *(float4*)(krow + (i << 2)) = *(const float4*)(ks + (i << 2));
        }
        // ---- stage Pt[q][j]: masked exp(leaky_relu(src+dst) - C) ----
        {
            unsigned mw = g_bm[(qt0 + pq) * NW + (j0 >> 5) + half];
            const float* dp = g_dstT + bh * N_ + j0 + (half << 5);
            #pragma unroll
            for (int g = 0; g < 8; g++) {
                float4 dv = *(const float4*)(dp + (g << 2));
                float l0 = sv + dv.x, l1 = sv + dv.y, l2 = sv + dv.z, l3 = sv + dv.w;
                l0 = fmaxf(l0, NEG_SLOPE * l0);
                l1 = fmaxf(l1, NEG_SLOPE * l1);
                l2 = fmaxf(l2, NEG_SLOPE * l2);
                l3 = fmaxf(l3, NEG_SLOPE * l3);
                float e0 = ex2f(fmaf(l0, LOG2E, -Cl));
                float e1 = ex2f(fmaf(l1, LOG2E, -Cl));
                float e2 = ex2f(fmaf(l2, LOG2E, -Cl));
                float e3 = ex2f(fmaf(l3, LOG2E, -Cl));
                unsigned mb = mw >> (g * 4);
                e0 = (mb & 1u) ? e0 : 0.f;
                e1 = (mb & 2u) ? e1 : 0.f;
                e2 = (mb & 4u) ? e2 : 0.f;
                e3 = (mb & 8u) ? e3 : 0.f;
                lsum += (e0 + e1) + (e2 + e3);
                *(float4*)(prow + (g << 2)) = make_float4(e0, e1, e2, e3);
            }
        }
        __syncthreads();
        // ---- GEMM: 8 k-steps of m16n8k8 tf32 across 8 n-tiles ----
        #pragma unroll
        for (int k = 0; k < 8; k++) {
            uint32_t a0, a1, a2, a3;
            LDSM4(a0, a1, a2, a3, aaddr0 + (k << 5));
            #pragma unroll
            for (int p = 0; p < 4; p++) {
                uint32_t b0, b1, b2, b3;
                LDSM4(b0, b1, b2, b3, baddr0[p] + (k << 5));
                MMA_TF32(acc[p][0], acc[p][1], acc[p][2], acc[p][3],
                         a0, a1, a2, a3, b0, b1);
                MMA_TF32(acc[p + 4][0], acc[p + 4][1], acc[p + 4][2], acc[p + 4][3],
                         a0, a1, a2, a3, b2, b3);
            }
        }
    }

    // ---- lsum combine across the two half-threads per q ----
    sRed[t] = lsum;
    __syncthreads();
    if (t < QTILE) sLs[t] = sRed[t] + sRed[t + QTILE];
    __syncthreads();

    // ---- epilogue: normalize + ELU + store from fragments ----
    {
        const int g  = lane >> 2;
        const int tc = (lane & 3) << 1;
        const int qa = q0 + g, qb = q0 + g + 8;
        const float inva = 1.f / sLs[qa];
        const float invb = 1.f / sLs[qb];
        float* opa = out + (rowbase + qt0 + qa) * HD_ + hh * D_ + tc;
        float* opb = out + (rowbase + qt0 + qb) * HD_ + hh * D_ + tc;
        #pragma unroll
        for (int nt = 0; nt < 8; nt++) {
            float v0 = acc[nt][0] * inva;
            float v1 = acc[nt][1] * inva;
            float v2 = acc[nt][2] * invb;
            float v3 = acc[nt][3] * invb;
            v0 = (v0 > 0.f) ? v0 : expm1f(v0);
            v1 = (v1 > 0.f) ? v1 : expm1f(v1);
            v2 = (v2 > 0.f) ? v2 : expm1f(v2);
            v3 = (v3 > 0.f) ? v3 : expm1f(v3);
            *(float2*)(opa + nt * 8) = make_float2(v0, v1);
            *(float2*)(opb + nt * 8) = make_float2(v2, v3);
        }
    }
}

// ---------------------------------------------------------------------------
extern "C" void kernel_launch(void* const* d_in, const int* in_sizes, int n_in,
                              void* d_out, int out_size) {
    const float* x      = (const float*)d_in[0];
    const int*   A_mask = (const int*)d_in[1];
    const float* W      = (const float*)d_in[2];
    const float* a_src  = (const float*)d_in[3];
    const float* a_dst  = (const float*)d_in[4];
    float* out = (float*)d_out;

    cudaFuncSetAttribute(k_attn, cudaFuncAttributeMaxDynamicSharedMemorySize,
                         SM_TOT * (int)sizeof(float));

    k_init<<<1, 32>>>();
    k_bitpack<<<(N_ * NW) / 256, 256>>>(A_mask);
    k_gemm<<<dim3(M_ / 64, HD_ / 64), 256>>>(x, W);
    k_srcdst<<<dim3(N_ / 256, B_ * H_), 256>>>(a_src, a_dst);
    k_attn<<<dim3(N_ / QTILE, B_ * H_), 256, SM_TOT * (int)sizeof(float)>>>(out);
}